// round 7
// baseline (speedup 1.0000x reference)
#include <cuda_runtime.h>
#include <cuda_bf16.h>
#include <math.h>
#include <stdint.h>

// ---------------------------------------------------------------------------
// SSAMBA encoder forward.  B=4, L=513, d_model=768, d_inner=1536, d_state=16,
// 24 layers, bidirectional Mamba, all fp32.
// GEMMs: 64/128 x 128 x 16 tiles, 256 thr, packed fma.rn.f32x2 (FFMA2).
// 64-row tiles on the big GEMMs to kill wave quantization (296-slot chip).
// Scan: one thread per chain, software-pipelined loads (prefetch t+1).
// ---------------------------------------------------------------------------

#define DM    768
#define DI    1536
#define DS    16
#define NB    4
#define LTOK  513
#define NROW  (NB*LTOK)          // 2052
#define NDEPTH 24

// ----------------------------- scratch -------------------------------------
__device__ __align__(256) float g_xp  [NB*512*256];
__device__ __align__(256) float g_ptok[NB*512*DM];
__device__ __align__(256) float g_h   [NROW*DM];
__device__ __align__(256) float g_res [NROW*DM];
__device__ __align__(256) float g_xn  [NROW*DM];
__device__ __align__(256) float g_xz  [NROW*2*DI];
__device__ __align__(256) float g_c0  [NROW*DI];
__device__ __align__(256) float g_c1  [NROW*DI];
__device__ __align__(256) float g_db0 [NROW*80];
__device__ __align__(256) float g_db1 [NROW*80];
__device__ __align__(256) float g_part[16*NROW*80];
__device__ __align__(256) float g_dtf [NROW*DI];
__device__ __align__(256) float g_dtb [NROW*DI];
__device__ __align__(256) float g_y0  [NROW*DI];
__device__ __align__(256) float g_y1  [NROW*DI];

// ----------------------------- helpers -------------------------------------
__device__ __forceinline__ unsigned long long pk2(float x, float y) {
    unsigned long long r;
    asm("mov.b64 %0, {%1,%2};" : "=l"(r) : "f"(x), "f"(y));
    return r;
}
__device__ __forceinline__ unsigned long long f2fma(unsigned long long a,
                                                    unsigned long long b,
                                                    unsigned long long c) {
    unsigned long long d;
    asm("fma.rn.f32x2 %0, %1, %2, %3;" : "=l"(d) : "l"(a), "l"(b), "l"(c));
    return d;
}
__device__ __forceinline__ void upk2(unsigned long long v, float& x, float& y) {
    asm("mov.b64 {%0,%1}, %2;" : "=f"(x), "=f"(y) : "l"(v));
}
__device__ __forceinline__ float softplusf(float x) {
    return x > 20.f ? x : log1pf(__expf(x));
}
__device__ __forceinline__ float siluf(float x) {
    return x * (1.f / (1.f + __expf(-x)));
}

__device__ __forceinline__ float blockReduceSum(float v) {
    __shared__ float red[8];
    int lane = threadIdx.x & 31, w = threadIdx.x >> 5;
    __syncthreads();
    #pragma unroll
    for (int o = 16; o > 0; o >>= 1) v += __shfl_xor_sync(0xffffffffu, v, o);
    if (lane == 0) red[w] = v;
    __syncthreads();
    if (w == 0) {
        float t = (lane < (int)(blockDim.x >> 5)) ? red[lane] : 0.f;
        #pragma unroll
        for (int o = 4; o > 0; o >>= 1) t += __shfl_xor_sync(0xffffffffu, t, o);
        if (lane == 0) red[0] = t;
    }
    __syncthreads();
    return red[0];
}

// ------------------------- GEMM core: C = A * B^T ---------------------------
// A: MxK row-major (lda), B: NxK row-major (ldb), C: MxN (ldc).
// If A2 != nullptr, effective A = 0.5*(A + A2).
// BMT: 128 (8x8/thread) or 64 (4x8/thread, doubles CTA count for wave fill).
// BK=16: 256 threads load with lrow=tid>>2, lc4=tid&3; A in BMT/64 passes,
// B in 2 passes.  All K in this net are multiples of 16 (48,192,256,768,1536).
#define BN 128
#define BKK 16

template<int BMT>
__device__ __forceinline__ void gemm_core(
    const float* __restrict__ A, const float* __restrict__ A2, int lda,
    const float* __restrict__ B, int ldb,
    float* __restrict__ C, int ldc,
    int M, int N, int K,
    const float* __restrict__ bias, int epi,
    int m0, int n0)
{
    constexpr int ACCM  = BMT / 32;      // f32x2 accumulators in m per thread
    constexpr int RPT   = BMT / 16;      // rows per thread in m
    constexpr int APASS = BMT / 64;      // A loader passes (1 or 2)
    __shared__ __align__(16) float As[BKK][BMT + 4];
    __shared__ __align__(16) float Bs[BKK][BN + 4];
    const int tid  = threadIdx.x;
    const int tx   = tid & 15;           // n sub-tile
    const int ty   = tid >> 4;           // m sub-tile
    const int lrow = tid >> 2;           // loader row (0..63)
    const int lc4  = tid & 3;            // loader float4 index along k (0..3)

    unsigned long long acc[ACCM][8];
    #pragma unroll
    for (int i = 0; i < ACCM; i++)
        #pragma unroll
        for (int j = 0; j < 8; j++) acc[i][j] = 0ull;

    float4 ra[APASS], rb[2];

    // ---- prologue load (kt = 0) ----
    #pragma unroll
    for (int p = 0; p < APASS; p++) {
        int m = m0 + lrow + p * 64;
        if (m < M) {
            ra[p] = *reinterpret_cast<const float4*>(A + (size_t)m * lda + lc4 * 4);
            if (A2) {
                float4 r2 = *reinterpret_cast<const float4*>(A2 + (size_t)m * lda + lc4 * 4);
                ra[p].x = 0.5f * (ra[p].x + r2.x); ra[p].y = 0.5f * (ra[p].y + r2.y);
                ra[p].z = 0.5f * (ra[p].z + r2.z); ra[p].w = 0.5f * (ra[p].w + r2.w);
            }
        } else ra[p] = make_float4(0.f, 0.f, 0.f, 0.f);
    }
    #pragma unroll
    for (int p = 0; p < 2; p++) {
        int n = n0 + lrow + p * 64;
        rb[p] = (n < N) ? *reinterpret_cast<const float4*>(B + (size_t)n * ldb + lc4 * 4)
                        : make_float4(0.f, 0.f, 0.f, 0.f);
    }

    for (int kt = 0; kt < K; kt += BKK) {
        // ---- store current regs into smem (k-major transpose) ----
        #pragma unroll
        for (int p = 0; p < APASS; p++) {
            int r = lrow + p * 64;
            As[lc4 * 4 + 0][r] = ra[p].x;
            As[lc4 * 4 + 1][r] = ra[p].y;
            As[lc4 * 4 + 2][r] = ra[p].z;
            As[lc4 * 4 + 3][r] = ra[p].w;
        }
        #pragma unroll
        for (int p = 0; p < 2; p++) {
            int r = lrow + p * 64;
            Bs[lc4 * 4 + 0][r] = rb[p].x;
            Bs[lc4 * 4 + 1][r] = rb[p].y;
            Bs[lc4 * 4 + 2][r] = rb[p].z;
            Bs[lc4 * 4 + 3][r] = rb[p].w;
        }
        __syncthreads();

        // ---- prefetch next tile into regs (hidden under compute) ----
        if (kt + BKK < K) {
            int kb = kt + BKK + lc4 * 4;
            #pragma unroll
            for (int p = 0; p < APASS; p++) {
                int m = m0 + lrow + p * 64;
                if (m < M) {
                    ra[p] = *reinterpret_cast<const float4*>(A + (size_t)m * lda + kb);
                    if (A2) {
                        float4 r2 = *reinterpret_cast<const float4*>(A2 + (size_t)m * lda + kb);
                        ra[p].x = 0.5f * (ra[p].x + r2.x); ra[p].y = 0.5f * (ra[p].y + r2.y);
                        ra[p].z = 0.5f * (ra[p].z + r2.z); ra[p].w = 0.5f * (ra[p].w + r2.w);
                    }
                } else ra[p] = make_float4(0.f, 0.f, 0.f, 0.f);
            }
            #pragma unroll
            for (int p = 0; p < 2; p++) {
                int n = n0 + lrow + p * 64;
                rb[p] = (n < N) ? *reinterpret_cast<const float4*>(B + (size_t)n * ldb + kb)
                                : make_float4(0.f, 0.f, 0.f, 0.f);
            }
        }

        // ---- compute on smem tile ----
        #pragma unroll
        for (int kk = 0; kk < BKK; kk++) {
            const unsigned long long* Ap =
                reinterpret_cast<const unsigned long long*>(&As[kk][ty * RPT]);
            unsigned long long am[ACCM];
            #pragma unroll
            for (int i = 0; i < ACCM; i++) am[i] = Ap[i];
            const float* Br = &Bs[kk][tx * 8];
            float4 b0 = *reinterpret_cast<const float4*>(Br);
            float4 b1 = *reinterpret_cast<const float4*>(Br + 4);
            float bf[8] = {b0.x, b0.y, b0.z, b0.w, b1.x, b1.y, b1.z, b1.w};
            #pragma unroll
            for (int j = 0; j < 8; j++) {
                unsigned long long bb = pk2(bf[j], bf[j]);
                #pragma unroll
                for (int i = 0; i < ACCM; i++)
                    acc[i][j] = f2fma(am[i], bb, acc[i][j]);
            }
        }
        __syncthreads();
    }

    #pragma unroll
    for (int i = 0; i < ACCM; i++) {
        #pragma unroll
        for (int j = 0; j < 8; j++) {
            float lo, hi;
            upk2(acc[i][j], lo, hi);
            int n = n0 + tx * 8 + j;
            int m = m0 + ty * RPT + 2 * i;
            if (n < N) {
                if (epi == 1) {
                    float bb = bias[n];
                    lo = softplusf(lo + bb);
                    hi = softplusf(hi + bb);
                }
                if (m < M)     C[(size_t)m * ldc + n]       = lo;
                if (m + 1 < M) C[(size_t)(m + 1) * ldc + n] = hi;
            }
        }
    }
}

// 128-row tile version (used where CTA count is already ample).
__global__ __launch_bounds__(256, 2) void k_gemm(
    const float* __restrict__ A, int lda, const float* __restrict__ B, int ldb,
    float* __restrict__ C, int ldc, int M, int N, int K)
{
    gemm_core<128>(A, nullptr, lda, B, ldb, C, ldc, M, N, K, nullptr, 0,
                   blockIdx.x * 128, blockIdx.y * BN);
}

// 64-row tile version — doubles CTA count to fill partial waves.
__global__ __launch_bounds__(256, 3) void k_gemm64(
    const float* __restrict__ A, int lda, const float* __restrict__ B, int ldb,
    float* __restrict__ C, int ldc, int M, int N, int K)
{
    gemm_core<64>(A, nullptr, lda, B, ldb, C, ldc, M, N, K, nullptr, 0,
                  blockIdx.x * 64, blockIdx.y * BN);
}

// w_out GEMM with fused combine: A_eff = 0.5*(y0 + y1).  64-row tiles.
__global__ __launch_bounds__(256, 3) void k_gemm_out(const float* __restrict__ wo)
{
    gemm_core<64>(g_y0, g_y1, DI, wo, DI, g_h, DM, NROW, DM, DI, nullptr, 0,
                  blockIdx.x * 64, blockIdx.y * BN);
}

// dt GEMM, both branches via grid.z, softplus(x + bias) epilogue.
// A rows are the first 48 cols of the 80-wide dbl buffers (lda = 80).
__global__ __launch_bounds__(256, 3) void k_gemm_dt(
    const float* __restrict__ wdt, const float* __restrict__ bdt)
{
    int br = blockIdx.z;
    gemm_core<64>(br ? g_db1 : g_db0, nullptr, 80,
                  wdt + (size_t)br * DI * 48, 48,
                  br ? g_dtb : g_dtf, DI,
                  NROW, DI, 48,
                  bdt + (size_t)br * DI, 1,
                  blockIdx.x * 64, blockIdx.y * BN);
}

// skinny w_x GEMM: split-K x 8, branches batched in grid.z; writes partials.
// 272 CTAs ~= 0.92 waves at 2/SM — already near-optimal, keep 128-row tiles.
__global__ __launch_bounds__(256, 2) void k_gemm_g2(const float* __restrict__ wx)
{
    int z  = blockIdx.z;
    int br = z >> 3, s = z & 7;
    const float* Asrc = (br ? g_c1 : g_c0) + s * 192;
    const float* Bsrc = wx + (size_t)br * 80 * DI + s * 192;
    float* Cdst = g_part + (size_t)(br * 8 + s) * NROW * 80;
    gemm_core<128>(Asrc, nullptr, DI, Bsrc, DI, Cdst, 80, NROW, 80, 192,
                   nullptr, 0, blockIdx.x * 128, 0);
}

__global__ void k_g2reduce()
{
    int idx = blockIdx.x * blockDim.x + threadIdx.x;
    if (idx >= 2 * NROW * 80) return;
    int br  = idx / (NROW * 80);
    int off = idx - br * (NROW * 80);
    const float* p = g_part + (size_t)br * 8 * NROW * 80 + off;
    float s = 0.f;
    #pragma unroll
    for (int i = 0; i < 8; i++) s += p[(size_t)i * NROW * 80];
    (br ? g_db1 : g_db0)[off] = s;
}

// --------------------------- front end -------------------------------------
__global__ void k_repack(const float* __restrict__ x)
{
    int idx = blockIdx.x * 256 + threadIdx.x;      // < 4*512*256
    int c     = idx & 255;
    int patch = (idx >> 8) & 511;
    int b     = idx >> 17;
    int p1 = c >> 4, p2 = c & 15;
    int f = patch >> 6, t = patch & 63;
    g_xp[idx] = x[(size_t)b * 131072 + (size_t)(f * 16 + p1) * 1024 + t * 16 + p2];
}

__global__ void k_assemble(const float* __restrict__ patch_b,
                           const float* __restrict__ cls,
                           const float* __restrict__ pos)
{
    int idx = blockIdx.x * 256 + threadIdx.x;
    if (idx >= NROW * DM) return;
    int d   = idx % DM;
    int row = idx / DM;
    int b = row / LTOK, l = row % LTOK;
    float v;
    if (l == 0) v = cls[d] + pos[d];
    else        v = g_ptok[((size_t)b * 512 + (l - 1)) * DM + d] + patch_b[d]
                    + pos[(size_t)l * DM + d];
    g_h[idx]   = v;
    g_res[idx] = 0.f;
}

// res += h ; xn = rmsnorm(res) * lnw
__global__ __launch_bounds__(256) void k_addnorm(const float* __restrict__ lnw)
{
    int r = blockIdx.x;
    size_t base = (size_t)r * DM;
    float v[3];
    float ss = 0.f;
    #pragma unroll
    for (int i = 0; i < 3; i++) {
        int d = threadIdx.x + i * 256;
        float t = g_h[base + d] + g_res[base + d];
        g_res[base + d] = t;
        v[i] = t;
        ss += t * t;
    }
    ss = blockReduceSum(ss);
    float sc = rsqrtf(ss * (1.f / DM) + 1e-5f);
    #pragma unroll
    for (int i = 0; i < 3; i++) {
        int d = threadIdx.x + i * 256;
        g_xn[base + d] = v[i] * sc * lnw[d];
    }
}

// depthwise causal conv (fwd + bwd) + silu.  u = g_xz[:, :DI].
__global__ void k_conv(const float* __restrict__ cw, const float* __restrict__ cb)
{
    int idx = blockIdx.x * 256 + threadIdx.x;      // < 2*NROW*DI
    int d    = idx % DI;
    int rowb = idx / DI;
    int row  = rowb % NROW;
    int br   = rowb / NROW;
    int b = row / LTOK, l = row % LTOK;

    const float* w = cw + ((size_t)br * DI + d) * 4;
    float acc = cb[(size_t)br * DI + d];
    size_t ub = ((size_t)b * LTOK) * (2 * DI) + d;
    if (br == 0) {
        #pragma unroll
        for (int k = 0; k < 4; k++) {
            int ls = l - 3 + k;
            if (ls >= 0) acc += w[k] * g_xz[ub + (size_t)ls * (2 * DI)];
        }
    } else {
        #pragma unroll
        for (int k = 0; k < 4; k++) {
            int ls = l + 3 - k;
            if (ls < LTOK) acc += w[k] * g_xz[ub + (size_t)ls * (2 * DI)];
        }
    }
    (br ? g_c1 : g_c0)[(size_t)row * DI + d] = siluf(acc);
}

// ------------------------------- SSM scan ----------------------------------
// One thread per (branch, batch, d) chain; 16 states in registers.
// Software-pipelined: step t+1's loads are issued before step t's compute so
// L2 latency overlaps the FMA/EX2 chain (only ~2.6 warps/SM available, so
// latency must be hidden by ILP, not occupancy).
// Fast path: if A[s] == (s+1)*A[0] (a_log = log(1..16)), one exp + power
// tree instead of 16 exps per step; generic fallback otherwise.
__global__ __launch_bounds__(64) void k_scan(const float* __restrict__ a_log,
                                             const float* __restrict__ dd)
{
    int g  = blockIdx.x * 64 + threadIdx.x;        // < 2*4*1536
    int d  = g % DI;
    int b  = (g / DI) % NB;
    int br = g / (DI * NB);

    const float* cbuf = br ? g_c1  : g_c0;
    const float* dtb  = br ? g_dtb : g_dtf;
    const float* db   = br ? g_db1 : g_db0;
    float*       yb   = br ? g_y1  : g_y0;

    float A[DS], hst[DS];
    const float* ap = a_log + ((size_t)br * DI + d) * DS;
    #pragma unroll
    for (int s = 0; s < DS; s++) { A[s] = -__expf(ap[s]); hst[s] = 0.f; }
    float Dv = dd[(size_t)br * DI + d];

    bool structured = true;
    #pragma unroll
    for (int s = 1; s < DS; s++) {
        float want = (float)(s + 1) * A[0];
        if (fabsf(A[s] - want) > 1e-4f * fmaxf(1.f, fabsf(want)))
            structured = false;
    }

    // ---- prologue: load step 0 ----
    int l0   = br ? (LTOK - 1) : 0;
    int rowc = b * LTOK + l0;
    float dt_c = dtb[(size_t)rowc * DI + d];
    float u_c  = cbuf[(size_t)rowc * DI + d];
    float z_c  = g_xz[(size_t)rowc * (2 * DI) + DI + d];
    float4 bc_c[8];
    {
        const float4* bp = reinterpret_cast<const float4*>(db + (size_t)rowc * 80 + 48);
        #pragma unroll
        for (int i = 0; i < 8; i++) bc_c[i] = bp[i];
    }

    for (int step = 0; step < LTOK; step++) {
        // ---- issue next step's loads first (independent of compute) ----
        float dt_n = 0.f, u_n = 0.f, z_n = 0.f;
        float4 bc_n[8];
        int rown = rowc;
        if (step + 1 < LTOK) {
            int ln = br ? (LTOK - 2 - step) : (step + 1);
            rown = b * LTOK + ln;
            dt_n = dtb[(size_t)rown * DI + d];
            u_n  = cbuf[(size_t)rown * DI + d];
            z_n  = g_xz[(size_t)rown * (2 * DI) + DI + d];
            const float4* bq = reinterpret_cast<const float4*>(db + (size_t)rown * 80 + 48);
            #pragma unroll
            for (int i = 0; i < 8; i++) bc_n[i] = bq[i];
        } else {
            #pragma unroll
            for (int i = 0; i < 8; i++) bc_n[i] = make_float4(0.f, 0.f, 0.f, 0.f);
        }

        // ---- compute current step ----
        const float* Bv = reinterpret_cast<const float*>(&bc_c[0]);
        const float* Cv = Bv + DS;
        float du = dt_c * u_c;
        float dA[DS];
        if (structured) {
            dA[0] = __expf(dt_c * A[0]);
            #pragma unroll
            for (int s = 1; s < DS; s++)
                dA[s] = dA[(s - 1) >> 1] * dA[s - 1 - ((s - 1) >> 1)];
        } else {
            #pragma unroll
            for (int s = 0; s < DS; s++) dA[s] = __expf(dt_c * A[s]);
        }
        float y = 0.f;
        #pragma unroll
        for (int s = 0; s < DS; s++) {
            hst[s] = dA[s] * hst[s] + du * Bv[s];
            y += hst[s] * Cv[s];
        }
        y += u_c * Dv;
        yb[(size_t)rowc * DI + d] = y * siluf(z_c);

        // ---- rotate pipeline ----
        rowc = rown;
        dt_c = dt_n; u_c = u_n; z_c = z_n;
        #pragma unroll
        for (int i = 0; i < 8; i++) bc_c[i] = bc_n[i];
    }
}

// ------------------------------ final LN -----------------------------------
__global__ __launch_bounds__(256) void k_final(const float* __restrict__ fw,
                                               const float* __restrict__ fb,
                                               float* __restrict__ out)
{
    int b = blockIdx.x;                    // 4 blocks, row l = 0
    size_t base = (size_t)b * LTOK * DM;
    float v[3];
    float s = 0.f;
    #pragma unroll
    for (int i = 0; i < 3; i++) {
        int d = threadIdx.x + i * 256;
        v[i] = g_res[base + d] + g_h[base + d];
        s += v[i];
    }
    s = blockReduceSum(s);
    float mean = s * (1.f / DM);
    float q = 0.f;
    #pragma unroll
    for (int i = 0; i < 3; i++) { float t = v[i] - mean; q += t * t; }
    q = blockReduceSum(q);
    float inv = rsqrtf(q * (1.f / DM) + 1e-5f);
    #pragma unroll
    for (int i = 0; i < 3; i++) {
        int d = threadIdx.x + i * 256;
        out[(size_t)b * DM + d] = (v[i] - mean) * inv * fw[d] + fb[d];
    }
}

// ------------------------------ launcher -----------------------------------
extern "C" void kernel_launch(void* const* d_in, const int* in_sizes, int n_in,
                              void* d_out, int out_size)
{
    const float* x       = (const float*)d_in[0];
    const float* patch_w = (const float*)d_in[1];
    const float* patch_b = (const float*)d_in[2];
    const float* cls     = (const float*)d_in[3];
    const float* pos     = (const float*)d_in[4];
    const float* ln_w    = (const float*)d_in[5];
    const float* w_in    = (const float*)d_in[6];
    const float* conv_w  = (const float*)d_in[7];
    const float* conv_b  = (const float*)d_in[8];
    const float* w_x     = (const float*)d_in[9];
    const float* w_dt    = (const float*)d_in[10];
    const float* b_dt    = (const float*)d_in[11];
    const float* a_log   = (const float*)d_in[12];
    const float* dd      = (const float*)d_in[13];
    const float* w_out   = (const float*)d_in[14];
    const float* fn_w    = (const float*)d_in[15];
    const float* fn_b    = (const float*)d_in[16];
    float* out = (float*)d_out;

    float *p_xp, *p_ptok, *p_xn, *p_xz;
    cudaGetSymbolAddress((void**)&p_xp,   g_xp);
    cudaGetSymbolAddress((void**)&p_ptok, g_ptok);
    cudaGetSymbolAddress((void**)&p_xn,   g_xn);
    cudaGetSymbolAddress((void**)&p_xz,   g_xz);

    // ---- front end: patch embed + token assembly ----
    k_repack<<<2048, 256>>>(x);
    {
        dim3 grid((NB * 512 + 63) / 64, (DM + BN - 1) / BN);
        k_gemm64<<<grid, 256>>>(p_xp, 256, patch_w, 256, p_ptok, DM,
                                NB * 512, DM, 256);
    }
    k_assemble<<<(NROW * DM + 255) / 256, 256>>>(patch_b, cls, pos);

    dim3 g_in ((NROW + 63) / 64, (2 * DI + BN - 1) / BN);
    dim3 g_g2 ((NROW + 127) / 128, 1, 16);
    dim3 g_dt ((NROW + 63) / 64, DI / BN, 2);
    dim3 g_out((NROW + 63) / 64, DM / BN);

    for (int i = 0; i < NDEPTH; i++) {
        const float* wi  = w_in  + (size_t)i * 2 * DI * DM;
        const float* cw  = conv_w + (size_t)i * 2 * DI * 4;
        const float* cb  = conv_b + (size_t)i * 2 * DI;
        const float* wx  = w_x   + (size_t)i * 2 * 80 * DI;
        const float* wdt = w_dt  + (size_t)i * 2 * DI * 48;
        const float* bdt = b_dt  + (size_t)i * 2 * DI;
        const float* al  = a_log + (size_t)i * 2 * DI * DS;
        const float* di  = dd    + (size_t)i * 2 * DI;
        const float* wo  = w_out + (size_t)i * DM * DI;

        k_addnorm<<<NROW, 256>>>(ln_w + (size_t)i * DM);
        k_gemm64<<<g_in, 256>>>(p_xn, DM, wi, DM, p_xz, 2 * DI, NROW, 2 * DI, DM);
        k_conv<<<2 * NROW * DI / 256, 256>>>(cw, cb);
        k_gemm_g2<<<g_g2, 256>>>(wx);
        k_g2reduce<<<(2 * NROW * 80 + 255) / 256, 256>>>();
        k_gemm_dt<<<g_dt, 256>>>(wdt, bdt);
        k_scan<<<2 * NB * DI / 64, 64>>>(al, di);
        k_gemm_out<<<g_out, 256>>>(wo);
    }

    k_final<<<NB, 256>>>(fn_w, fn_b, out);
    (void)in_sizes; (void)n_in; (void)out_size;
}

// round 10
// speedup vs baseline: 1.7228x; 1.7228x over previous
#include <cuda_runtime.h>
#include <cuda_bf16.h>
#include <math.h>
#include <stdint.h>

// ---------------------------------------------------------------------------
// SSAMBAEncoder forward.  B=4, L=513, d_model=768, d_inner=1536, d_state=16,
// 24 layers, bidirectional Mamba, all fp32.
// Big GEMMs (w_in, w_out): tensor-core split-bf16 (hi/lo, 3 MMAs) emulated
// fp32 via mma.sync m16n8k16.  Small GEMMs: fp32 FFMA2 path.
// Scan: one thread per chain, software-pipelined loads (prefetch t+1).
// ---------------------------------------------------------------------------

#define DM    768
#define DI    1536
#define DS    16
#define NB    4
#define LTOK  513
#define NROW  (NB*LTOK)          // 2052
#define NDEPTH 24

// ----------------------------- scratch -------------------------------------
__device__ __align__(256) float g_xp  [NB*512*256];
__device__ __align__(256) float g_ptok[NB*512*DM];
__device__ __align__(256) float g_h   [NROW*DM];
__device__ __align__(256) float g_res [NROW*DM];
__device__ __align__(256) float g_xn  [NROW*DM];
__device__ __align__(256) float g_xz  [NROW*2*DI];
__device__ __align__(256) float g_c0  [NROW*DI];
__device__ __align__(256) float g_c1  [NROW*DI];
__device__ __align__(256) float g_db0 [NROW*80];
__device__ __align__(256) float g_db1 [NROW*80];
__device__ __align__(256) float g_part[16*NROW*80];
__device__ __align__(256) float g_dtf [NROW*DI];
__device__ __align__(256) float g_dtb [NROW*DI];
__device__ __align__(256) float g_y0  [NROW*DI];
__device__ __align__(256) float g_y1  [NROW*DI];

// ----------------------------- helpers -------------------------------------
__device__ __forceinline__ unsigned long long pk2(float x, float y) {
    unsigned long long r;
    asm("mov.b64 %0, {%1,%2};" : "=l"(r) : "f"(x), "f"(y));
    return r;
}
__device__ __forceinline__ unsigned long long f2fma(unsigned long long a,
                                                    unsigned long long b,
                                                    unsigned long long c) {
    unsigned long long d;
    asm("fma.rn.f32x2 %0, %1, %2, %3;" : "=l"(d) : "l"(a), "l"(b), "l"(c));
    return d;
}
__device__ __forceinline__ void upk2(unsigned long long v, float& x, float& y) {
    asm("mov.b64 {%0,%1}, %2;" : "=f"(x), "=f"(y) : "l"(v));
}
__device__ __forceinline__ float softplusf(float x) {
    return x > 20.f ? x : log1pf(__expf(x));
}
__device__ __forceinline__ float siluf(float x) {
    return x * (1.f / (1.f + __expf(-x)));
}

__device__ __forceinline__ float blockReduceSum(float v) {
    __shared__ float red[8];
    int lane = threadIdx.x & 31, w = threadIdx.x >> 5;
    __syncthreads();
    #pragma unroll
    for (int o = 16; o > 0; o >>= 1) v += __shfl_xor_sync(0xffffffffu, v, o);
    if (lane == 0) red[w] = v;
    __syncthreads();
    if (w == 0) {
        float t = (lane < (int)(blockDim.x >> 5)) ? red[lane] : 0.f;
        #pragma unroll
        for (int o = 4; o > 0; o >>= 1) t += __shfl_xor_sync(0xffffffffu, t, o);
        if (lane == 0) red[0] = t;
    }
    __syncthreads();
    return red[0];
}

// ====================== tensor-core split-bf16 GEMM =========================
// C = A(MxK,f32) * B(NxK,f32)^T, fp32 accum on tensor cores.
// a = ah + al (bf16 each); a*b ~= ah*bh + ah*bl + al*bh.
// Tile: BM=64, BN=128, BK=32.  256 threads = 8 warps (2m x 4n), each warp
// computes 32x32 via 2x4 m16n8k16 fragments.
#define TBK 32
#define TSA 40    // padded bf16 row stride: 80B, 16B-multiple, conflict-free

__device__ __forceinline__ uint32_t smem_u32(const void* p) {
    return (uint32_t)__cvta_generic_to_shared(p);
}
__device__ __forceinline__ void ldsm_x4(uint32_t& r0, uint32_t& r1,
                                        uint32_t& r2, uint32_t& r3, uint32_t a) {
    asm volatile("ldmatrix.sync.aligned.m8n8.x4.shared.b16 {%0,%1,%2,%3}, [%4];"
                 : "=r"(r0), "=r"(r1), "=r"(r2), "=r"(r3) : "r"(a));
}
__device__ __forceinline__ void mma_bf16(float& d0, float& d1, float& d2, float& d3,
                                         uint32_t a0, uint32_t a1, uint32_t a2, uint32_t a3,
                                         uint32_t b0, uint32_t b1) {
    asm volatile("mma.sync.aligned.m16n8k16.row.col.f32.bf16.bf16.f32 "
                 "{%0,%1,%2,%3}, {%4,%5,%6,%7}, {%8,%9}, {%0,%1,%2,%3};"
                 : "+f"(d0), "+f"(d1), "+f"(d2), "+f"(d3)
                 : "r"(a0), "r"(a1), "r"(a2), "r"(a3), "r"(b0), "r"(b1));
}

// convert float4 (4 consecutive k) into hi/lo bf16x2 pairs and store.
__device__ __forceinline__ void cvt_store(__nv_bfloat16* hrow, __nv_bfloat16* lrow,
                                          int col, float4 v) {
    __nv_bfloat162 h01 = __floats2bfloat162_rn(v.x, v.y);
    __nv_bfloat162 h23 = __floats2bfloat162_rn(v.z, v.w);
    __nv_bfloat162 l01 = __floats2bfloat162_rn(v.x - __low2float(h01),
                                               v.y - __high2float(h01));
    __nv_bfloat162 l23 = __floats2bfloat162_rn(v.z - __low2float(h23),
                                               v.w - __high2float(h23));
    *reinterpret_cast<__nv_bfloat162*>(hrow + col)     = h01;
    *reinterpret_cast<__nv_bfloat162*>(hrow + col + 2) = h23;
    *reinterpret_cast<__nv_bfloat162*>(lrow + col)     = l01;
    *reinterpret_cast<__nv_bfloat162*>(lrow + col + 2) = l23;
}

__device__ __forceinline__ void tgemm_core(
    const float* __restrict__ A, const float* __restrict__ A2, int lda,
    const float* __restrict__ B, int ldb,
    float* __restrict__ C, int ldc,
    int M, int N, int K, int m0, int n0)
{
    __shared__ __align__(16) __nv_bfloat16 Ah[64][TSA], Al[64][TSA];
    __shared__ __align__(16) __nv_bfloat16 Bh[128][TSA], Bl[128][TSA];
    const int tid  = threadIdx.x;
    const int lrow = tid >> 2;          // 0..63
    const int lc4  = tid & 3;           // float4 slot within 16 k
    const int lane = tid & 31;
    const int wid  = tid >> 5;
    const int mw   = wid & 1;           // m-half (0..1) -> 32 rows
    const int nw   = wid >> 1;          // n-quarter (0..3) -> 32 cols

    float acc[2][4][4];
    #pragma unroll
    for (int i = 0; i < 2; i++)
        #pragma unroll
        for (int j = 0; j < 4; j++)
            #pragma unroll
            for (int k = 0; k < 4; k++) acc[i][j][k] = 0.f;

    // ldmatrix lane-address components (constant across k-loop)
    const int a_r  = (lane & 7) + ((lane >> 3) & 1) * 8;   // + mt*16 + mw*32
    const int a_kc = ((lane >> 4) & 1) * 8;                // + kh
    const int b_r  = (lane & 7) + ((lane >> 4) & 1) * 8;   // + q*16 + nw*32
    const int b_kc = ((lane >> 3) & 1) * 8;                // + kh

    float4 ra[2], rb[4];
    {   // prologue load (kt = 0)
        int m = m0 + lrow;
        #pragma unroll
        for (int c = 0; c < 2; c++) {
            if (m < M) {
                ra[c] = *reinterpret_cast<const float4*>(A + (size_t)m * lda + c * 16 + lc4 * 4);
                if (A2) {
                    float4 r2 = *reinterpret_cast<const float4*>(A2 + (size_t)m * lda + c * 16 + lc4 * 4);
                    ra[c].x = 0.5f * (ra[c].x + r2.x); ra[c].y = 0.5f * (ra[c].y + r2.y);
                    ra[c].z = 0.5f * (ra[c].z + r2.z); ra[c].w = 0.5f * (ra[c].w + r2.w);
                }
            } else ra[c] = make_float4(0.f, 0.f, 0.f, 0.f);
        }
        #pragma unroll
        for (int p = 0; p < 2; p++)
            #pragma unroll
            for (int c = 0; c < 2; c++) {
                int n = n0 + lrow + p * 64;
                rb[p * 2 + c] = (n < N)
                    ? *reinterpret_cast<const float4*>(B + (size_t)n * ldb + c * 16 + lc4 * 4)
                    : make_float4(0.f, 0.f, 0.f, 0.f);
            }
    }

    for (int kt = 0; kt < K; kt += TBK) {
        // ---- convert + store current regs into smem planes ----
        #pragma unroll
        for (int c = 0; c < 2; c++)
            cvt_store(Ah[lrow], Al[lrow], c * 16 + lc4 * 4, ra[c]);
        #pragma unroll
        for (int p = 0; p < 2; p++)
            #pragma unroll
            for (int c = 0; c < 2; c++)
                cvt_store(Bh[lrow + p * 64], Bl[lrow + p * 64],
                          c * 16 + lc4 * 4, rb[p * 2 + c]);
        __syncthreads();

        // ---- prefetch next k-tile ----
        if (kt + TBK < K) {
            int kb = kt + TBK + lc4 * 4;
            int m = m0 + lrow;
            #pragma unroll
            for (int c = 0; c < 2; c++) {
                if (m < M) {
                    ra[c] = *reinterpret_cast<const float4*>(A + (size_t)m * lda + kb + c * 16);
                    if (A2) {
                        float4 r2 = *reinterpret_cast<const float4*>(A2 + (size_t)m * lda + kb + c * 16);
                        ra[c].x = 0.5f * (ra[c].x + r2.x); ra[c].y = 0.5f * (ra[c].y + r2.y);
                        ra[c].z = 0.5f * (ra[c].z + r2.z); ra[c].w = 0.5f * (ra[c].w + r2.w);
                    }
                } else ra[c] = make_float4(0.f, 0.f, 0.f, 0.f);
            }
            #pragma unroll
            for (int p = 0; p < 2; p++)
                #pragma unroll
                for (int c = 0; c < 2; c++) {
                    int n = n0 + lrow + p * 64;
                    rb[p * 2 + c] = (n < N)
                        ? *reinterpret_cast<const float4*>(B + (size_t)n * ldb + kb + c * 16)
                        : make_float4(0.f, 0.f, 0.f, 0.f);
                }
        }

        // ---- tensor compute: two k16 halves ----
        #pragma unroll
        for (int kh = 0; kh < TBK; kh += 16) {
            uint32_t ah[2][4], alr[2][4];
            #pragma unroll
            for (int mt = 0; mt < 2; mt++) {
                int r = mw * 32 + mt * 16 + a_r;
                int kc = kh + a_kc;
                ldsm_x4(ah[mt][0],  ah[mt][1],  ah[mt][2],  ah[mt][3],
                        smem_u32(&Ah[r][kc]));
                ldsm_x4(alr[mt][0], alr[mt][1], alr[mt][2], alr[mt][3],
                        smem_u32(&Al[r][kc]));
            }
            uint32_t bh[4][2], bl[4][2];
            #pragma unroll
            for (int q = 0; q < 2; q++) {
                int r = nw * 32 + q * 16 + b_r;
                int kc = kh + b_kc;
                uint32_t t0, t1, t2, t3;
                ldsm_x4(t0, t1, t2, t3, smem_u32(&Bh[r][kc]));
                bh[2 * q][0] = t0; bh[2 * q][1] = t1;
                bh[2 * q + 1][0] = t2; bh[2 * q + 1][1] = t3;
                ldsm_x4(t0, t1, t2, t3, smem_u32(&Bl[r][kc]));
                bl[2 * q][0] = t0; bl[2 * q][1] = t1;
                bl[2 * q + 1][0] = t2; bl[2 * q + 1][1] = t3;
            }
            #pragma unroll
            for (int mt = 0; mt < 2; mt++)
                #pragma unroll
                for (int nt = 0; nt < 4; nt++) {
                    float* d = acc[mt][nt];
                    mma_bf16(d[0], d[1], d[2], d[3],
                             ah[mt][0], ah[mt][1], ah[mt][2], ah[mt][3],
                             bh[nt][0], bh[nt][1]);
                    mma_bf16(d[0], d[1], d[2], d[3],
                             ah[mt][0], ah[mt][1], ah[mt][2], ah[mt][3],
                             bl[nt][0], bl[nt][1]);
                    mma_bf16(d[0], d[1], d[2], d[3],
                             alr[mt][0], alr[mt][1], alr[mt][2], alr[mt][3],
                             bh[nt][0], bh[nt][1]);
                }
        }
        __syncthreads();
    }

    // ---- epilogue (N here is always a multiple of 128; guard M only) ----
    #pragma unroll
    for (int mt = 0; mt < 2; mt++)
        #pragma unroll
        for (int nt = 0; nt < 4; nt++) {
            int m = m0 + mw * 32 + mt * 16 + (lane >> 2);
            int n = n0 + nw * 32 + nt * 8 + (lane & 3) * 2;
            if (m < M)
                *reinterpret_cast<float2*>(&C[(size_t)m * ldc + n]) =
                    make_float2(acc[mt][nt][0], acc[mt][nt][1]);
            if (m + 8 < M)
                *reinterpret_cast<float2*>(&C[(size_t)(m + 8) * ldc + n]) =
                    make_float2(acc[mt][nt][2], acc[mt][nt][3]);
        }
}

__global__ __launch_bounds__(256, 2) void k_tgemm(
    const float* __restrict__ A, int lda, const float* __restrict__ B, int ldb,
    float* __restrict__ C, int ldc, int M, int N, int K)
{
    tgemm_core(A, nullptr, lda, B, ldb, C, ldc, M, N, K,
               blockIdx.x * 64, blockIdx.y * 128);
}

// w_out GEMM with fused combine: A_eff = 0.5*(y0 + y1).
__global__ __launch_bounds__(256, 2) void k_tgemm_out(const float* __restrict__ wo)
{
    tgemm_core(g_y0, g_y1, DI, wo, DI, g_h, DM, NROW, DM, DI,
               blockIdx.x * 64, blockIdx.y * 128);
}

// ------------------------- fp32 GEMM core (small GEMMs) ---------------------
#define BN 128
#define BKK 16

template<int BMT>
__device__ __forceinline__ void gemm_core(
    const float* __restrict__ A, int lda,
    const float* __restrict__ B, int ldb,
    float* __restrict__ C, int ldc,
    int M, int N, int K,
    const float* __restrict__ bias, int epi,
    int m0, int n0)
{
    constexpr int ACCM  = BMT / 32;
    constexpr int RPT   = BMT / 16;
    constexpr int APASS = BMT / 64;
    __shared__ __align__(16) float As[BKK][BMT + 4];
    __shared__ __align__(16) float Bs[BKK][BN + 4];
    const int tid  = threadIdx.x;
    const int tx   = tid & 15;
    const int ty   = tid >> 4;
    const int lrow = tid >> 2;
    const int lc4  = tid & 3;

    unsigned long long acc[ACCM][8];
    #pragma unroll
    for (int i = 0; i < ACCM; i++)
        #pragma unroll
        for (int j = 0; j < 8; j++) acc[i][j] = 0ull;

    float4 ra[APASS], rb[2];
    #pragma unroll
    for (int p = 0; p < APASS; p++) {
        int m = m0 + lrow + p * 64;
        ra[p] = (m < M) ? *reinterpret_cast<const float4*>(A + (size_t)m * lda + lc4 * 4)
                        : make_float4(0.f, 0.f, 0.f, 0.f);
    }
    #pragma unroll
    for (int p = 0; p < 2; p++) {
        int n = n0 + lrow + p * 64;
        rb[p] = (n < N) ? *reinterpret_cast<const float4*>(B + (size_t)n * ldb + lc4 * 4)
                        : make_float4(0.f, 0.f, 0.f, 0.f);
    }

    for (int kt = 0; kt < K; kt += BKK) {
        #pragma unroll
        for (int p = 0; p < APASS; p++) {
            int r = lrow + p * 64;
            As[lc4 * 4 + 0][r] = ra[p].x;
            As[lc4 * 4 + 1][r] = ra[p].y;
            As[lc4 * 4 + 2][r] = ra[p].z;
            As[lc4 * 4 + 3][r] = ra[p].w;
        }
        #pragma unroll
        for (int p = 0; p < 2; p++) {
            int r = lrow + p * 64;
            Bs[lc4 * 4 + 0][r] = rb[p].x;
            Bs[lc4 * 4 + 1][r] = rb[p].y;
            Bs[lc4 * 4 + 2][r] = rb[p].z;
            Bs[lc4 * 4 + 3][r] = rb[p].w;
        }
        __syncthreads();

        if (kt + BKK < K) {
            int kb = kt + BKK + lc4 * 4;
            #pragma unroll
            for (int p = 0; p < APASS; p++) {
                int m = m0 + lrow + p * 64;
                ra[p] = (m < M) ? *reinterpret_cast<const float4*>(A + (size_t)m * lda + kb)
                                : make_float4(0.f, 0.f, 0.f, 0.f);
            }
            #pragma unroll
            for (int p = 0; p < 2; p++) {
                int n = n0 + lrow + p * 64;
                rb[p] = (n < N) ? *reinterpret_cast<const float4*>(B + (size_t)n * ldb + kb)
                                : make_float4(0.f, 0.f, 0.f, 0.f);
            }
        }

        #pragma unroll
        for (int kk = 0; kk < BKK; kk++) {
            const unsigned long long* Ap =
                reinterpret_cast<const unsigned long long*>(&As[kk][ty * RPT]);
            unsigned long long am[ACCM];
            #pragma unroll
            for (int i = 0; i < ACCM; i++) am[i] = Ap[i];
            const float* Br = &Bs[kk][tx * 8];
            float4 b0 = *reinterpret_cast<const float4*>(Br);
            float4 b1 = *reinterpret_cast<const float4*>(Br + 4);
            float bf[8] = {b0.x, b0.y, b0.z, b0.w, b1.x, b1.y, b1.z, b1.w};
            #pragma unroll
            for (int j = 0; j < 8; j++) {
                unsigned long long bb = pk2(bf[j], bf[j]);
                #pragma unroll
                for (int i = 0; i < ACCM; i++)
                    acc[i][j] = f2fma(am[i], bb, acc[i][j]);
            }
        }
        __syncthreads();
    }

    #pragma unroll
    for (int i = 0; i < ACCM; i++) {
        #pragma unroll
        for (int j = 0; j < 8; j++) {
            float lo, hi;
            upk2(acc[i][j], lo, hi);
            int n = n0 + tx * 8 + j;
            int m = m0 + ty * RPT + 2 * i;
            if (n < N) {
                if (epi == 1) {
                    float bb = bias[n];
                    lo = softplusf(lo + bb);
                    hi = softplusf(hi + bb);
                }
                if (m < M)     C[(size_t)m * ldc + n]       = lo;
                if (m + 1 < M) C[(size_t)(m + 1) * ldc + n] = hi;
            }
        }
    }
}

__global__ __launch_bounds__(256, 3) void k_gemm64(
    const float* __restrict__ A, int lda, const float* __restrict__ B, int ldb,
    float* __restrict__ C, int ldc, int M, int N, int K)
{
    gemm_core<64>(A, lda, B, ldb, C, ldc, M, N, K, nullptr, 0,
                  blockIdx.x * 64, blockIdx.y * BN);
}

__global__ __launch_bounds__(256, 3) void k_gemm_dt(
    const float* __restrict__ wdt, const float* __restrict__ bdt)
{
    int br = blockIdx.z;
    gemm_core<64>(br ? g_db1 : g_db0, 80,
                  wdt + (size_t)br * DI * 48, 48,
                  br ? g_dtb : g_dtf, DI,
                  NROW, DI, 48,
                  bdt + (size_t)br * DI, 1,
                  blockIdx.x * 64, blockIdx.y * BN);
}

__global__ __launch_bounds__(256, 2) void k_gemm_g2(const float* __restrict__ wx)
{
    int z  = blockIdx.z;
    int br = z >> 3, s = z & 7;
    const float* Asrc = (br ? g_c1 : g_c0) + s * 192;
    const float* Bsrc = wx + (size_t)br * 80 * DI + s * 192;
    float* Cdst = g_part + (size_t)(br * 8 + s) * NROW * 80;
    gemm_core<128>(Asrc, DI, Bsrc, DI, Cdst, 80, NROW, 80, 192,
                   nullptr, 0, blockIdx.x * 128, 0);
}

__global__ void k_g2reduce()
{
    int idx = blockIdx.x * blockDim.x + threadIdx.x;
    if (idx >= 2 * NROW * 80) return;
    int br  = idx / (NROW * 80);
    int off = idx - br * (NROW * 80);
    const float* p = g_part + (size_t)br * 8 * NROW * 80 + off;
    float s = 0.f;
    #pragma unroll
    for (int i = 0; i < 8; i++) s += p[(size_t)i * NROW * 80];
    (br ? g_db1 : g_db0)[off] = s;
}

// --------------------------- front end -------------------------------------
__global__ void k_repack(const float* __restrict__ x)
{
    int idx = blockIdx.x * 256 + threadIdx.x;
    int c     = idx & 255;
    int patch = (idx >> 8) & 511;
    int b     = idx >> 17;
    int p1 = c >> 4, p2 = c & 15;
    int f = patch >> 6, t = patch & 63;
    g_xp[idx] = x[(size_t)b * 131072 + (size_t)(f * 16 + p1) * 1024 + t * 16 + p2];
}

__global__ void k_assemble(const float* __restrict__ patch_b,
                           const float* __restrict__ cls,
                           const float* __restrict__ pos)
{
    int idx = blockIdx.x * 256 + threadIdx.x;
    if (idx >= NROW * DM) return;
    int d   = idx % DM;
    int row = idx / DM;
    int b = row / LTOK, l = row % LTOK;
    float v;
    if (l == 0) v = cls[d] + pos[d];
    else        v = g_ptok[((size_t)b * 512 + (l - 1)) * DM + d] + patch_b[d]
                    + pos[(size_t)l * DM + d];
    g_h[idx]   = v;
    g_res[idx] = 0.f;
}

__global__ __launch_bounds__(256) void k_addnorm(const float* __restrict__ lnw)
{
    int r = blockIdx.x;
    size_t base = (size_t)r * DM;
    float v[3];
    float ss = 0.f;
    #pragma unroll
    for (int i = 0; i < 3; i++) {
        int d = threadIdx.x + i * 256;
        float t = g_h[base + d] + g_res[base + d];
        g_res[base + d] = t;
        v[i] = t;
        ss += t * t;
    }
    ss = blockReduceSum(ss);
    float sc = rsqrtf(ss * (1.f / DM) + 1e-5f);
    #pragma unroll
    for (int i = 0; i < 3; i++) {
        int d = threadIdx.x + i * 256;
        g_xn[base + d] = v[i] * sc * lnw[d];
    }
}

__global__ void k_conv(const float* __restrict__ cw, const float* __restrict__ cb)
{
    int idx = blockIdx.x * 256 + threadIdx.x;
    int d    = idx % DI;
    int rowb = idx / DI;
    int row  = rowb % NROW;
    int br   = rowb / NROW;
    int b = row / LTOK, l = row % LTOK;

    const float* w = cw + ((size_t)br * DI + d) * 4;
    float acc = cb[(size_t)br * DI + d];
    size_t ub = ((size_t)b * LTOK) * (2 * DI) + d;
    if (br == 0) {
        #pragma unroll
        for (int k = 0; k < 4; k++) {
            int ls = l - 3 + k;
            if (ls >= 0) acc += w[k] * g_xz[ub + (size_t)ls * (2 * DI)];
        }
    } else {
        #pragma unroll
        for (int k = 0; k < 4; k++) {
            int ls = l + 3 - k;
            if (ls < LTOK) acc += w[k] * g_xz[ub + (size_t)ls * (2 * DI)];
        }
    }
    (br ? g_c1 : g_c0)[(size_t)row * DI + d] = siluf(acc);
}

// ------------------------------- SSM scan ----------------------------------
__global__ __launch_bounds__(64) void k_scan(const float* __restrict__ a_log,
                                             const float* __restrict__ dd)
{
    int g  = blockIdx.x * 64 + threadIdx.x;
    int d  = g % DI;
    int b  = (g / DI) % NB;
    int br = g / (DI * NB);

    const float* cbuf = br ? g_c1  : g_c0;
    const float* dtb  = br ? g_dtb : g_dtf;
    const float* db   = br ? g_db1 : g_db0;
    float*       yb   = br ? g_y1  : g_y0;

    float A[DS], hst[DS];
    const float* ap = a_log + ((size_t)br * DI + d) * DS;
    #pragma unroll
    for (int s = 0; s < DS; s++) { A[s] = -__expf(ap[s]); hst[s] = 0.f; }
    float Dv = dd[(size_t)br * DI + d];

    bool structured = true;
    #pragma unroll
    for (int s = 1; s < DS; s++) {
        float want = (float)(s + 1) * A[0];
        if (fabsf(A[s] - want) > 1e-4f * fmaxf(1.f, fabsf(want)))
            structured = false;
    }

    int l0   = br ? (LTOK - 1) : 0;
    int rowc = b * LTOK + l0;
    float dt_c = dtb[(size_t)rowc * DI + d];
    float u_c  = cbuf[(size_t)rowc * DI + d];
    float z_c  = g_xz[(size_t)rowc * (2 * DI) + DI + d];
    float4 bc_c[8];
    {
        const float4* bp = reinterpret_cast<const float4*>(db + (size_t)rowc * 80 + 48);
        #pragma unroll
        for (int i = 0; i < 8; i++) bc_c[i] = bp[i];
    }

    for (int step = 0; step < LTOK; step++) {
        float dt_n = 0.f, u_n = 0.f, z_n = 0.f;
        float4 bc_n[8];
        int rown = rowc;
        if (step + 1 < LTOK) {
            int ln = br ? (LTOK - 2 - step) : (step + 1);
            rown = b * LTOK + ln;
            dt_n = dtb[(size_t)rown * DI + d];
            u_n  = cbuf[(size_t)rown * DI + d];
            z_n  = g_xz[(size_t)rown * (2 * DI) + DI + d];
            const float4* bq = reinterpret_cast<const float4*>(db + (size_t)rown * 80 + 48);
            #pragma unroll
            for (int i = 0; i < 8; i++) bc_n[i] = bq[i];
        } else {
            #pragma unroll
            for (int i = 0; i < 8; i++) bc_n[i] = make_float4(0.f, 0.f, 0.f, 0.f);
        }

        const float* Bv = reinterpret_cast<const float*>(&bc_c[0]);
        const float* Cv = Bv + DS;
        float du = dt_c * u_c;
        float dA[DS];
        if (structured) {
            dA[0] = __expf(dt_c * A[0]);
            #pragma unroll
            for (int s = 1; s < DS; s++)
                dA[s] = dA[(s - 1) >> 1] * dA[s - 1 - ((s - 1) >> 1)];
        } else {
            #pragma unroll
            for (int s = 0; s < DS; s++) dA[s] = __expf(dt_c * A[s]);
        }
        float y = 0.f;
        #pragma unroll
        for (int s = 0; s < DS; s++) {
            hst[s] = dA[s] * hst[s] + du * Bv[s];
            y += hst[s] * Cv[s];
        }
        y += u_c * Dv;
        yb[(size_t)rowc * DI + d] = y * siluf(z_c);

        rowc = rown;
        dt_c = dt_n; u_c = u_n; z_c = z_n;
        #pragma unroll
        for (int i = 0; i < 8; i++) bc_c[i] = bc_n[i];
    }
}

// ------------------------------ final LN -----------------------------------
__global__ __launch_bounds__(256) void k_final(const float* __restrict__ fw,
                                               const float* __restrict__ fb,
                                               float* __restrict__ out)
{
    int b = blockIdx.x;
    size_t base = (size_t)b * LTOK * DM;
    float v[3];
    float s = 0.f;
    #pragma unroll
    for (int i = 0; i < 3; i++) {
        int d = threadIdx.x + i * 256;
        v[i] = g_res[base + d] + g_h[base + d];
        s += v[i];
    }
    s = blockReduceSum(s);
    float mean = s * (1.f / DM);
    float q = 0.f;
    #pragma unroll
    for (int i = 0; i < 3; i++) { float t = v[i] - mean; q += t * t; }
    q = blockReduceSum(q);
    float inv = rsqrtf(q * (1.f / DM) + 1e-5f);
    #pragma unroll
    for (int i = 0; i < 3; i++) {
        int d = threadIdx.x + i * 256;
        out[(size_t)b * DM + d] = (v[i] - mean) * inv * fw[d] + fb[d];
    }
}

// ------------------------------ launcher -----------------------------------
extern "C" void kernel_launch(void* const* d_in, const int* in_sizes, int n_in,
                              void* d_out, int out_size)
{
    const float* x       = (const float*)d_in[0];
    const float* patch_w = (const float*)d_in[1];
    const float* patch_b = (const float*)d_in[2];
    const float* cls     = (const float*)d_in[3];
    const float* pos     = (const float*)d_in[4];
    const float* ln_w    = (const float*)d_in[5];
    const float* w_in    = (const float*)d_in[6];
    const float* conv_w  = (const float*)d_in[7];
    const float* conv_b  = (const float*)d_in[8];
    const float* w_x     = (const float*)d_in[9];
    const float* w_dt    = (const float*)d_in[10];
    const float* b_dt    = (const float*)d_in[11];
    const float* a_log   = (const float*)d_in[12];
    const float* dd      = (const float*)d_in[13];
    const float* w_out   = (const float*)d_in[14];
    const float* fn_w    = (const float*)d_in[15];
    const float* fn_b    = (const float*)d_in[16];
    float* out = (float*)d_out;

    float *p_xp, *p_ptok, *p_xn, *p_xz;
    cudaGetSymbolAddress((void**)&p_xp,   g_xp);
    cudaGetSymbolAddress((void**)&p_ptok, g_ptok);
    cudaGetSymbolAddress((void**)&p_xn,   g_xn);
    cudaGetSymbolAddress((void**)&p_xz,   g_xz);

    // ---- front end: patch embed + token assembly ----
    k_repack<<<2048, 256>>>(x);
    {
        dim3 grid((NB * 512 + 63) / 64, (DM + BN - 1) / BN);
        k_gemm64<<<grid, 256>>>(p_xp, 256, patch_w, 256, p_ptok, DM,
                                NB * 512, DM, 256);
    }
    k_assemble<<<(NROW * DM + 255) / 256, 256>>>(patch_b, cls, pos);

    dim3 g_in ((NROW + 63) / 64, (2 * DI) / 128);
    dim3 g_g2 ((NROW + 127) / 128, 1, 16);
    dim3 g_dt ((NROW + 63) / 64, DI / BN, 2);
    dim3 g_out((NROW + 63) / 64, DM / 128);

    for (int i = 0; i < NDEPTH; i++) {
        const float* wi  = w_in  + (size_t)i * 2 * DI * DM;
        const float* cw  = conv_w + (size_t)i * 2 * DI * 4;
        const float* cb  = conv_b + (size_t)i * 2 * DI;
        const float* wx  = w_x   + (size_t)i * 2 * 80 * DI;
        const float* wdt = w_dt  + (size_t)i * 2 * DI * 48;
        const float* bdt = b_dt  + (size_t)i * 2 * DI;
        const float* al  = a_log + (size_t)i * 2 * DI * DS;
        const float* di  = dd    + (size_t)i * 2 * DI;
        const float* wo  = w_out + (size_t)i * DM * DI;

        k_addnorm<<<NROW, 256>>>(ln_w + (size_t)i * DM);
        k_tgemm<<<g_in, 256>>>(p_xn, DM, wi, DM, p_xz, 2 * DI, NROW, 2 * DI, DM);
        k_conv<<<2 * NROW * DI / 256, 256>>>(cw, cb);
        k_gemm_g2<<<g_g2, 256>>>(wx);
        k_g2reduce<<<(2 * NROW * 80 + 255) / 256, 256>>>();
        k_gemm_dt<<<g_dt, 256>>>(wdt, bdt);
        k_scan<<<2 * NB * DI / 64, 64>>>(al, di);
        k_tgemm_out<<<g_out, 256>>>(wo);
    }

    k_final<<<NB, 256>>>(fn_w, fn_b, out);
    (void)in_sizes; (void)n_in; (void)out_size;
}